// round 12
// baseline (speedup 1.0000x reference)
#include <cuda_runtime.h>
#include <cuda_bf16.h>
#include <cstdint>
#include <math.h>

#define BB 2
#define NN 2048
#define CC 384
#define HH 6
#define DD 64
#define TCC 1152   // 3*C
#define MM 4096    // B*N

typedef __nv_bfloat16 bf16;

// ---------------- device scratch (int8 levels except V / bf16) ----------------
__device__ int8_t g_wqkv8[TCC * CC];
__device__ int8_t g_wproj8[CC * CC];
__device__ int8_t g_xq8[(size_t)MM * CC];
__device__ int8_t g_q8[BB * HH * NN * DD];
__device__ int8_t g_k8[BB * HH * NN * DD];
__device__ bf16   g_v[BB * HH * NN * DD];
__device__ int8_t g_o8[(size_t)MM * CC];

// ---------------- helpers ----------------
__device__ __forceinline__ float qlvl(float x, float inv_alpha) {
    float s = x * inv_alpha;
    s = fminf(fmaxf(s, -128.f), 127.f);
    return rintf(s);
}
__device__ __forceinline__ int qi(float x, float inv_alpha) {
    float s = x * inv_alpha;
    s = fminf(fmaxf(s, -128.f), 127.f);
    return __float2int_rn(s);
}
__device__ __forceinline__ uint32_t pack4(int b0, int b1, int b2, int b3) {
    return (uint32_t)(b0 & 0xff) | ((uint32_t)(b1 & 0xff) << 8) |
           ((uint32_t)(b2 & 0xff) << 16) | ((uint32_t)(b3 & 0xff) << 24);
}

__device__ __forceinline__ void mma16816(float* c, const uint32_t* a,
                                         uint32_t b0, uint32_t b1) {
    asm volatile(
        "mma.sync.aligned.m16n8k16.row.col.f32.bf16.bf16.f32 "
        "{%0,%1,%2,%3}, {%4,%5,%6,%7}, {%8,%9}, {%0,%1,%2,%3};\n"
        : "+f"(c[0]), "+f"(c[1]), "+f"(c[2]), "+f"(c[3])
        : "r"(a[0]), "r"(a[1]), "r"(a[2]), "r"(a[3]), "r"(b0), "r"(b1));
}
__device__ __forceinline__ void imma16832(int* c, const uint32_t* a,
                                          uint32_t b0, uint32_t b1) {
    asm volatile(
        "mma.sync.aligned.m16n8k32.row.col.s32.s8.s8.s32 "
        "{%0,%1,%2,%3}, {%4,%5,%6,%7}, {%8,%9}, {%0,%1,%2,%3};\n"
        : "+r"(c[0]), "+r"(c[1]), "+r"(c[2]), "+r"(c[3])
        : "r"(a[0]), "r"(a[1]), "r"(a[2]), "r"(a[3]), "r"(b0), "r"(b1));
}

__device__ __forceinline__ uint32_t sptr(const void* p) {
    return (uint32_t)__cvta_generic_to_shared(p);
}
__device__ __forceinline__ void ldsm4(uint32_t* r, uint32_t addr) {
    asm volatile("ldmatrix.sync.aligned.m8n8.x4.shared.b16 {%0,%1,%2,%3},[%4];\n"
                 : "=r"(r[0]), "=r"(r[1]), "=r"(r[2]), "=r"(r[3]) : "r"(addr));
}
__device__ __forceinline__ void ldsm4t(uint32_t* r, uint32_t addr) {
    asm volatile("ldmatrix.sync.aligned.m8n8.x4.trans.shared.b16 {%0,%1,%2,%3},[%4];\n"
                 : "=r"(r[0]), "=r"(r[1]), "=r"(r[2]), "=r"(r[3]) : "r"(addr));
}
__device__ __forceinline__ void cpa16(uint32_t d, const void* s) {
    asm volatile("cp.async.cg.shared.global [%0], [%1], 16;\n" :: "r"(d), "l"(s));
}
__device__ __forceinline__ void cpcommit() {
    asm volatile("cp.async.commit_group;\n");
}
template <int N>
__device__ __forceinline__ void cpwait() {
    asm volatile("cp.async.wait_group %0;\n" :: "n"(N));
}

// ---------------- kernel 1: quantize x + weights to int8 levels ----------------
__global__ __launch_bounds__(256) void k_quant(
        const float* __restrict__ x,
        const float* __restrict__ wqkv, const float* __restrict__ wproj,
        const float* __restrict__ a_qkv_w, const float* __restrict__ a_proj_w,
        const float* __restrict__ a_qkv_a) {
    float i1 = 1.f / a_qkv_w[0];
    float i2 = 1.f / a_proj_w[0];
    float i3 = 1.f / a_qkv_a[0];
    int i4 = (blockIdx.x * 256 + threadIdx.x) * 4;

    if (i4 < MM * CC) {
        float4 v = *(const float4*)&x[i4];
        *(uint32_t*)&g_xq8[i4] =
            pack4(qi(v.x, i3), qi(v.y, i3), qi(v.z, i3), qi(v.w, i3));
    }
    if (i4 < TCC * CC) {
        float4 v = *(const float4*)&wqkv[i4];
        *(uint32_t*)&g_wqkv8[i4] =
            pack4(qi(v.x, i1), qi(v.y, i1), qi(v.z, i1), qi(v.w, i1));
    }
    if (i4 < CC * CC) {
        float4 v = *(const float4*)&wproj[i4];
        *(uint32_t*)&g_wproj8[i4] =
            pack4(qi(v.x, i2), qi(v.y, i2), qi(v.z, i2), qi(v.w, i2));
    }
}

// ---------------- kernel 2: QKV int8 GEMM 4096x1152x384, CTA 64x128, 3-stage ----------------
// smem rows viewed as u16 (each u16 = 2 int8 along K). K-tile = 64 bytes.
__global__ __launch_bounds__(256) void k_qkv(
        const float* __restrict__ a_qkv_a, const float* __restrict__ a_qkv_w,
        const float* __restrict__ a_q, const float* __restrict__ a_k,
        const float* __restrict__ a_v) {
    __shared__ uint16_t sA[3][64][40];
    __shared__ uint16_t sB[3][128][40];

    int tid = threadIdx.x, lane = tid & 31, wid = tid >> 5;
    int wm = wid & 3, wn = wid >> 2;
    int gr = lane >> 2, gc = (lane & 3) * 2;
    int lr_a = lane & 15, lc_a = (lane >> 4) << 3;
    int lr_b = ((lane >> 4) << 3) + (lane & 7), lc_b = ((lane >> 3) & 1) << 3;
    int m0 = blockIdx.x * 64, n0 = blockIdx.y * 128;

    int ra = tid >> 2, ca = tid & 3;          // A: 64 rows x 4 16B-chunks
    int rb = tid >> 2, cb = tid & 3;          // B half: 64 rows x 4 chunks (x2)

    int acc[8][4];
    #pragma unroll
    for (int i = 0; i < 8; i++)
        #pragma unroll
        for (int c = 0; c < 4; c++) acc[i][c] = 0;

    // prologue: prefetch kt = 0, 1 (k-tile = 64 bytes)
    #pragma unroll
    for (int p = 0; p < 2; p++) {
        int kb = p * 64;
        cpa16(sptr(&sA[p][ra][ca * 8]), &g_xq8[(size_t)(m0 + ra) * CC + kb + ca * 16]);
        cpa16(sptr(&sB[p][rb][cb * 8]), &g_wqkv8[(size_t)(n0 + rb) * CC + kb + cb * 16]);
        cpa16(sptr(&sB[p][rb + 64][cb * 8]), &g_wqkv8[(size_t)(n0 + rb + 64) * CC + kb + cb * 16]);
        cpcommit();
    }

    for (int kt = 0; kt < 6; kt++) {
        if (kt <= 3) cpwait<1>(); else cpwait<0>();
        __syncthreads();
        if (kt <= 3) {
            int st = (kt + 2) % 3, kb = (kt + 2) * 64;
            cpa16(sptr(&sA[st][ra][ca * 8]), &g_xq8[(size_t)(m0 + ra) * CC + kb + ca * 16]);
            cpa16(sptr(&sB[st][rb][cb * 8]), &g_wqkv8[(size_t)(n0 + rb) * CC + kb + cb * 16]);
            cpa16(sptr(&sB[st][rb + 64][cb * 8]), &g_wqkv8[(size_t)(n0 + rb + 64) * CC + kb + cb * 16]);
            cpcommit();
        }
        int buf = kt % 3;
        #pragma unroll
        for (int kc = 0; kc < 2; kc++) {           // kc = 32-byte (k32) chunk
            uint32_t af[4];
            ldsm4(af, sptr(&sA[buf][wm * 16 + lr_a][kc * 16 + lc_a]));
            #pragma unroll
            for (int np = 0; np < 4; np++) {
                uint32_t bfr[4];
                ldsm4(bfr, sptr(&sB[buf][wn * 64 + np * 16 + lr_b][kc * 16 + lc_b]));
                imma16832(acc[2 * np], af, bfr[0], bfr[1]);
                imma16832(acc[2 * np + 1], af, bfr[2], bfr[3]);
            }
        }
    }

    int which = (n0 >= 768) ? 2 : (n0 >= 384 ? 1 : 0);
    const float* a3 = (which == 0) ? a_q : (which == 1 ? a_k : a_v);
    float inv3 = 1.f / a3[0];
    float sAB = a_qkv_a[0] * a_qkv_w[0];
    int ncol0 = n0 - which * CC;
    #pragma unroll
    for (int nc = 0; nc < 8; nc++)
        #pragma unroll
        for (int h2 = 0; h2 < 2; h2++) {
            int row = m0 + wm * 16 + gr + h2 * 8;
            int col = ncol0 + wn * 64 + nc * 8 + gc;
            int b = row >> 11, n = row & 2047;
            int h = col >> 6, d = col & 63;
            float v0 = (float)acc[nc][2 * h2] * sAB;
            float v1 = (float)acc[nc][2 * h2 + 1] * sAB;
            size_t off = (((size_t)(b * HH + h)) * NN + n) * DD + d;
            if (which == 2) {
                __nv_bfloat162 pr;
                pr.x = __float2bfloat16(qlvl(v0, inv3));
                pr.y = __float2bfloat16(qlvl(v1, inv3));
                *(__nv_bfloat162*)&g_v[off] = pr;
            } else {
                int l0 = qi(v0, inv3), l1 = qi(v1, inv3);
                uint16_t pk = (uint16_t)((l0 & 0xff) | ((l1 & 0xff) << 8));
                int8_t* dst = (which == 0) ? g_q8 : g_k8;
                *(uint16_t*)&dst[off] = pk;
            }
        }
}

// ---------------- kernel 3: fused attention, 64 Q rows/CTA, QK int8 / PV bf16 ----------------
__global__ __launch_bounds__(128) void k_attn(
        const float* __restrict__ a_q, const float* __restrict__ a_k,
        const float* __restrict__ a_attn, const float* __restrict__ a_attn2,
        const float* __restrict__ a_v, const float* __restrict__ a_proj_a) {
    __shared__ uint16_t sKa[4][64][40];   // int8 K tiles (64 rows x 64 bytes) as u16
    __shared__ bf16 sV[2][64][72];
    __shared__ float lut[256];

    int tid = threadIdx.x, lane = tid & 31, wid = tid >> 5;
    int gr = lane >> 2, gc = (lane & 3) * 2;
    int lr_a = lane & 15, lc_a = (lane >> 4) << 3;
    int lr_b = ((lane >> 4) << 3) + (lane & 7), lc_b = ((lane >> 3) & 1) << 3;
    int bh = blockIdx.y;
    int rt0 = blockIdx.x * 64;
    int wr = wid * 16;

    float aat = a_attn[0];
    float fsc = a_q[0] * a_k[0] * 0.125f / aat;   // scale = D^-0.5 = 1/8

    #pragma unroll
    for (int i = tid; i < 256; i += 128) lut[i] = expf(-(float)i * aat);

    const int8_t* kbase = g_k8 + (size_t)bh * NN * DD;
    const bf16*   vbase = g_v + (size_t)bh * NN * DD;

    // stage Q (64 rows x 64 bytes) into sKa[0], build resident A fragments
    const int8_t* qptr = g_q8 + ((size_t)bh * NN + rt0) * DD;
    #pragma unroll
    for (int t = 0; t < 2; t++) {
        int idx = tid + t * 128;
        int r = idx >> 2, c16 = idx & 3;
        *(uint4*)&sKa[0][r][c16 * 8] = *(const uint4*)&qptr[(size_t)r * DD + c16 * 16];
    }
    __syncthreads();
    uint32_t qf[2][4];
    #pragma unroll
    for (int kc = 0; kc < 2; kc++)
        ldsm4(qf[kc], sptr(&sKa[0][wr + lr_a][kc * 16 + lc_a]));
    __syncthreads();

    float tl[2] = {0.f, 0.f};

    // pass-1 prologue: prefetch K tiles 0,1,2 into stages 0,1,2 (each 4KB)
    #pragma unroll
    for (int p = 0; p < 3; p++) {
        const int8_t* kp = kbase + (size_t)p * 64 * DD;
        #pragma unroll
        for (int t = 0; t < 2; t++) {
            int idx = tid + t * 128;
            int r = idx >> 2, c16 = idx & 3;
            cpa16(sptr(&sKa[p][r][c16 * 8]), &kp[(size_t)r * DD + c16 * 16]);
        }
        cpcommit();
    }

    // ---------- pass 1: row sums of exp((l-127)*a) ----------
    for (int ct = 0; ct < 32; ct++) {
        if (ct <= 28) cpwait<2>(); else cpwait<0>();
        __syncthreads();
        if (ct <= 28) {
            const int8_t* kp = kbase + (size_t)(ct + 3) * 64 * DD;
            int st = (ct + 3) & 3;
            #pragma unroll
            for (int t = 0; t < 2; t++) {
                int idx = tid + t * 128;
                int r = idx >> 2, c16 = idx & 3;
                cpa16(sptr(&sKa[st][r][c16 * 8]), &kp[(size_t)r * DD + c16 * 16]);
            }
            cpcommit();
        }
        uint16_t(*Kb)[40] = sKa[ct & 3];

        int sacc[8][4];
        #pragma unroll
        for (int i = 0; i < 8; i++)
            #pragma unroll
            for (int c = 0; c < 4; c++) sacc[i][c] = 0;
        #pragma unroll
        for (int ks = 0; ks < 2; ks++)
            #pragma unroll
            for (int np = 0; np < 4; np++) {
                uint32_t bfr[4];
                ldsm4(bfr, sptr(&Kb[np * 16 + lr_b][ks * 16 + lc_b]));
                imma16832(sacc[2 * np], qf[ks], bfr[0], bfr[1]);
                imma16832(sacc[2 * np + 1], qf[ks], bfr[2], bfr[3]);
            }

        #pragma unroll
        for (int nc = 0; nc < 8; nc++)
            #pragma unroll
            for (int h2 = 0; h2 < 2; h2++) {
                int l0 = qi(__int2float_rn(sacc[nc][2 * h2]), 0.f) ; // placeholder (unused)
                (void)l0;
                int i0 = __float2int_rn(fminf(fmaxf(__int2float_rn(sacc[nc][2 * h2]) * fsc, -128.f), 127.f));
                int i1 = __float2int_rn(fminf(fmaxf(__int2float_rn(sacc[nc][2 * h2 + 1]) * fsc, -128.f), 127.f));
                tl[h2] += lut[127 - i0] + lut[127 - i1];
            }
    }

    // pass-2 prologue: K0 -> sKa[0], V0 -> sV[0]
    #pragma unroll
    for (int t = 0; t < 2; t++) {
        int idx = tid + t * 128;
        int r = idx >> 2, c16 = idx & 3;
        cpa16(sptr(&sKa[0][r][c16 * 8]), &kbase[(size_t)r * DD + c16 * 16]);
    }
    #pragma unroll
    for (int t = 0; t < 4; t++) {
        int idx = tid + t * 128;
        int r = idx >> 3, c8 = (idx & 7) * 8;
        cpa16(sptr(&sV[0][r][c8]), &vbase[(size_t)r * DD + c8]);
    }
    cpcommit();

    // quad sum-reduce -> lane-local inverse sums
    float inva2 = 1.f / a_attn2[0];
    float liq[2];
    #pragma unroll
    for (int h2 = 0; h2 < 2; h2++) {
        tl[h2] += __shfl_xor_sync(0xffffffff, tl[h2], 1);
        tl[h2] += __shfl_xor_sync(0xffffffff, tl[h2], 2);
        liq[h2] = inva2 / tl[h2];
    }

    // ---------- pass 2: recompute S (int8), P in registers (bf16), P*V ----------
    float oacc[8][4];
    #pragma unroll
    for (int i = 0; i < 8; i++)
        #pragma unroll
        for (int c = 0; c < 4; c++) oacc[i][c] = 0.f;

    for (int ct = 0; ct < 32; ct++) {
        cpwait<0>();
        __syncthreads();
        if (ct < 31) {
            const int8_t* kp = kbase + (size_t)(ct + 1) * 64 * DD;
            const bf16*   vp = vbase + (size_t)(ct + 1) * 64 * DD;
            int stk = (ct + 1) & 1, stv = (ct + 1) & 1;
            #pragma unroll
            for (int t = 0; t < 2; t++) {
                int idx = tid + t * 128;
                int r = idx >> 2, c16 = idx & 3;
                cpa16(sptr(&sKa[stk][r][c16 * 8]), &kp[(size_t)r * DD + c16 * 16]);
            }
            #pragma unroll
            for (int t = 0; t < 4; t++) {
                int idx = tid + t * 128;
                int r = idx >> 3, c8 = (idx & 7) * 8;
                cpa16(sptr(&sV[stv][r][c8]), &vp[(size_t)r * DD + c8]);
            }
            cpcommit();
        }
        uint16_t(*Kb)[40] = sKa[ct & 1];
        bf16(*Vb)[72] = sV[ct & 1];

        int sacc[8][4];
        #pragma unroll
        for (int i = 0; i < 8; i++)
            #pragma unroll
            for (int c = 0; c < 4; c++) sacc[i][c] = 0;
        #pragma unroll
        for (int ks = 0; ks < 2; ks++)
            #pragma unroll
            for (int np = 0; np < 4; np++) {
                uint32_t bfr[4];
                ldsm4(bfr, sptr(&Kb[np * 16 + lr_b][ks * 16 + lc_b]));
                imma16832(sacc[2 * np], qf[ks], bfr[0], bfr[1]);
                imma16832(sacc[2 * np + 1], qf[ks], bfr[2], bfr[3]);
            }

        // S (s32) -> P level fragments (bf16 A-layout), in registers
        uint32_t pf[4][4];
        #pragma unroll
        for (int kc = 0; kc < 4; kc++) {
            int nc = 2 * kc, ncb = 2 * kc + 1;
            #pragma unroll
            for (int slot = 0; slot < 4; slot++) {
                int src = (slot & 2) ? ncb : nc;
                int h2 = slot & 1;
                float s0 = __int2float_rn(h2 ? sacc[src][2] : sacc[src][0]) * fsc;
                float s1 = __int2float_rn(h2 ? sacc[src][3] : sacc[src][1]) * fsc;
                int l0 = __float2int_rn(fminf(fmaxf(s0, -128.f), 127.f));
                int l1 = __float2int_rn(fminf(fmaxf(s1, -128.f), 127.f));
                float p0 = rintf(fminf(lut[127 - l0] * liq[h2], 127.f));
                float p1 = rintf(fminf(lut[127 - l1] * liq[h2], 127.f));
                __nv_bfloat162 pr;
                pr.x = __float2bfloat16(p0);
                pr.y = __float2bfloat16(p1);
                pf[kc][slot] = *(uint32_t*)&pr;
            }
        }

        // P (16x64 bf16) x V (64x64 bf16)
        #pragma unroll
        for (int ks = 0; ks < 4; ks++)
            #pragma unroll
            for (int np = 0; np < 4; np++) {
                uint32_t bfr[4];
                ldsm4t(bfr, sptr(&Vb[ks * 16 + lr_a][np * 16 + lc_a]));
                mma16816(oacc[2 * np], pf[ks], bfr[0], bfr[1]);
                mma16816(oacc[2 * np + 1], pf[ks], bfr[2], bfr[3]);
            }
    }

    // epilogue: scale, quantize with a_proj_a, store int8 levels to g_o8
    int b = bh / HH, h = bh % HH;
    float so = a_attn2[0] * a_v[0];
    float invpa = 1.f / a_proj_a[0];
    #pragma unroll
    for (int nc = 0; nc < 8; nc++)
        #pragma unroll
        for (int h2 = 0; h2 < 2; h2++) {
            int n = rt0 + wr + gr + h2 * 8;
            int d = nc * 8 + gc;
            int l0 = qi(oacc[nc][2 * h2] * so, invpa);
            int l1 = qi(oacc[nc][2 * h2 + 1] * so, invpa);
            uint16_t pk = (uint16_t)((l0 & 0xff) | ((l1 & 0xff) << 8));
            *(uint16_t*)&g_o8[((size_t)(b * NN + n)) * CC + h * 64 + d] = pk;
        }
}

// ---------------- kernel 4: projection int8 GEMM 4096x384x384 + bias, CTA 64x64 ----------------
__global__ __launch_bounds__(256) void k_proj(
        float* __restrict__ out, const float* __restrict__ bproj,
        const float* __restrict__ a_proj_a, const float* __restrict__ a_proj_w) {
    __shared__ uint16_t sA[3][64][40];
    __shared__ uint16_t sB[3][64][40];

    int tid = threadIdx.x, lane = tid & 31, wid = tid >> 5;
    int wm = wid & 3, wn = wid >> 2;
    int gr = lane >> 2, gc = (lane & 3) * 2;
    int lr_a = lane & 15, lc_a = (lane >> 4) << 3;
    int lr_b = ((lane >> 4) << 3) + (lane & 7), lc_b = ((lane >> 3) & 1) << 3;
    int m0 = blockIdx.x * 64, n0 = blockIdx.y * 64;

    int ra = tid >> 2, ca = tid & 3;

    int acc[4][4];
    #pragma unroll
    for (int i = 0; i < 4; i++)
        #pragma unroll
        for (int c = 0; c < 4; c++) acc[i][c] = 0;

    #pragma unroll
    for (int p = 0; p < 2; p++) {
        int kb = p * 64;
        cpa16(sptr(&sA[p][ra][ca * 8]), &g_o8[(size_t)(m0 + ra) * CC + kb + ca * 16]);
        cpa16(sptr(&sB[p][ra][ca * 8]), &g_wproj8[(size_t)(n0 + ra) * CC + kb + ca * 16]);
        cpcommit();
    }

    for (int kt = 0; kt < 6; kt++) {
        if (kt <= 3) cpwait<1>(); else cpwait<0>();
        __syncthreads();
        if (kt <= 3) {
            int st = (kt + 2) % 3, kb = (kt + 2) * 64;
            cpa16(sptr(&sA[st][ra][ca * 8]), &g_o8[(size_t)(m0 + ra) * CC + kb + ca * 16]);
            cpa16(sptr(&sB[st][ra][ca * 8]), &g_wproj8[(size_t)(n0 + ra) * CC + kb + ca * 16]);
            cpcommit();
        }
        int buf = kt % 3;
        #pragma unroll
        for (int kc = 0; kc < 2; kc++) {
            uint32_t af[4];
            ldsm4(af, sptr(&sA[buf][wm * 16 + lr_a][kc * 16 + lc_a]));
            #pragma unroll
            for (int np = 0; np < 2; np++) {
                uint32_t bfr[4];
                ldsm4(bfr, sptr(&sB[buf][wn * 32 + np * 16 + lr_b][kc * 16 + lc_b]));
                imma16832(acc[2 * np], af, bfr[0], bfr[1]);
                imma16832(acc[2 * np + 1], af, bfr[2], bfr[3]);
            }
        }
    }

    float sc = a_proj_a[0] * a_proj_w[0];
    #pragma unroll
    for (int jj = 0; jj < 4; jj++)
        #pragma unroll
        for (int h2 = 0; h2 < 2; h2++) {
            int row = m0 + wm * 16 + gr + h2 * 8;
            int col = n0 + wn * 32 + jj * 8 + gc;
            float2 r2;
            r2.x = (float)acc[jj][2 * h2] * sc + bproj[col];
            r2.y = (float)acc[jj][2 * h2 + 1] * sc + bproj[col + 1];
            *(float2*)&out[(size_t)row * CC + col] = r2;
        }
}

// ---------------- launch ----------------
extern "C" void kernel_launch(void* const* d_in, const int* in_sizes, int n_in,
                              void* d_out, int out_size) {
    const float* x        = (const float*)d_in[0];
    const float* wqkv     = (const float*)d_in[1];
    const float* wproj    = (const float*)d_in[2];
    const float* bproj    = (const float*)d_in[3];
    const float* a_qkv_w  = (const float*)d_in[4];
    const float* a_qkv_a  = (const float*)d_in[5];
    const float* a_proj_w = (const float*)d_in[6];
    const float* a_proj_a = (const float*)d_in[7];
    const float* a_q      = (const float*)d_in[8];
    const float* a_k      = (const float*)d_in[9];
    const float* a_v      = (const float*)d_in[10];
    const float* a_attn   = (const float*)d_in[11];
    const float* a_attn2  = (const float*)d_in[12];
    float* out = (float*)d_out;

    k_quant<<<(MM * CC / 4 + 255) / 256, 256>>>(x, wqkv, wproj, a_qkv_w, a_proj_w, a_qkv_a);
    k_qkv<<<dim3(64, 9), 256>>>(a_qkv_a, a_qkv_w, a_q, a_k, a_v);
    k_attn<<<dim3(32, 12), 128>>>(a_q, a_k, a_attn, a_attn2, a_v, a_proj_a);
    k_proj<<<dim3(64, 6), 256>>>(out, bproj, a_proj_a, a_proj_w);
}

// round 13
// speedup vs baseline: 1.4021x; 1.4021x over previous
#include <cuda_runtime.h>
#include <cuda_bf16.h>
#include <cstdint>
#include <math.h>

#define BB 2
#define NN 2048
#define CC 384
#define HH 6
#define DD 64
#define TCC 1152   // 3*C
#define MM 4096    // B*N

typedef __nv_bfloat16 bf16;

// ---------------- device scratch ----------------
__device__ bf16 g_wqkv[TCC * CC];
__device__ bf16 g_wproj[CC * CC];
__device__ bf16 g_xq[(size_t)MM * CC];
__device__ bf16 g_q[BB * HH * NN * DD];
__device__ bf16 g_k[BB * HH * NN * DD];
__device__ bf16 g_v[BB * HH * NN * DD];
__device__ bf16 g_o[(size_t)MM * CC];
__device__ float g_lp[2][BB * HH][NN];   // partial softmax row sums

// ---------------- helpers ----------------
__device__ __forceinline__ float qlvl(float x, float inv_alpha) {
    float s = x * inv_alpha;
    s = fminf(fmaxf(s, -128.f), 127.f);
    return rintf(s);
}

__device__ __forceinline__ void mma16816(float* c, const uint32_t* a,
                                         uint32_t b0, uint32_t b1) {
    asm volatile(
        "mma.sync.aligned.m16n8k16.row.col.f32.bf16.bf16.f32 "
        "{%0,%1,%2,%3}, {%4,%5,%6,%7}, {%8,%9}, {%0,%1,%2,%3};\n"
        : "+f"(c[0]), "+f"(c[1]), "+f"(c[2]), "+f"(c[3])
        : "r"(a[0]), "r"(a[1]), "r"(a[2]), "r"(a[3]), "r"(b0), "r"(b1));
}

__device__ __forceinline__ uint32_t sptr(const void* p) {
    return (uint32_t)__cvta_generic_to_shared(p);
}
__device__ __forceinline__ void ldsm4(uint32_t* r, uint32_t addr) {
    asm volatile("ldmatrix.sync.aligned.m8n8.x4.shared.b16 {%0,%1,%2,%3},[%4];\n"
                 : "=r"(r[0]), "=r"(r[1]), "=r"(r[2]), "=r"(r[3]) : "r"(addr));
}
__device__ __forceinline__ void ldsm4t(uint32_t* r, uint32_t addr) {
    asm volatile("ldmatrix.sync.aligned.m8n8.x4.trans.shared.b16 {%0,%1,%2,%3},[%4];\n"
                 : "=r"(r[0]), "=r"(r[1]), "=r"(r[2]), "=r"(r[3]) : "r"(addr));
}
__device__ __forceinline__ void cpa16(uint32_t d, const void* s) {
    asm volatile("cp.async.cg.shared.global [%0], [%1], 16;\n" :: "r"(d), "l"(s));
}
__device__ __forceinline__ void cpcommit() {
    asm volatile("cp.async.commit_group;\n");
}
template <int N>
__device__ __forceinline__ void cpwait() {
    asm volatile("cp.async.wait_group %0;\n" :: "n"(N));
}

// ---------------- kernel 1: quantize weights + x to bf16 levels ----------------
__global__ __launch_bounds__(256) void k_quant(
        const float* __restrict__ x,
        const float* __restrict__ wqkv, const float* __restrict__ wproj,
        const float* __restrict__ a_qkv_w, const float* __restrict__ a_proj_w,
        const float* __restrict__ a_qkv_a) {
    float i1 = 1.f / a_qkv_w[0];
    float i2 = 1.f / a_proj_w[0];
    float i3 = 1.f / a_qkv_a[0];
    int i4 = (blockIdx.x * 256 + threadIdx.x) * 4;

    if (i4 < MM * CC) {
        float4 v = *(const float4*)&x[i4];
        __nv_bfloat162 p0, p1;
        p0.x = __float2bfloat16(qlvl(v.x, i3));
        p0.y = __float2bfloat16(qlvl(v.y, i3));
        p1.x = __float2bfloat16(qlvl(v.z, i3));
        p1.y = __float2bfloat16(qlvl(v.w, i3));
        *(__nv_bfloat162*)&g_xq[i4] = p0;
        *(__nv_bfloat162*)&g_xq[i4 + 2] = p1;
    }
    if (i4 < TCC * CC) {
        float4 v = *(const float4*)&wqkv[i4];
        __nv_bfloat162 p0, p1;
        p0.x = __float2bfloat16(qlvl(v.x, i1));
        p0.y = __float2bfloat16(qlvl(v.y, i1));
        p1.x = __float2bfloat16(qlvl(v.z, i1));
        p1.y = __float2bfloat16(qlvl(v.w, i1));
        *(__nv_bfloat162*)&g_wqkv[i4] = p0;
        *(__nv_bfloat162*)&g_wqkv[i4 + 2] = p1;
    }
    if (i4 < CC * CC) {
        float4 v = *(const float4*)&wproj[i4];
        __nv_bfloat162 p0, p1;
        p0.x = __float2bfloat16(qlvl(v.x, i2));
        p0.y = __float2bfloat16(qlvl(v.y, i2));
        p1.x = __float2bfloat16(qlvl(v.z, i2));
        p1.y = __float2bfloat16(qlvl(v.w, i2));
        *(__nv_bfloat162*)&g_wproj[i4] = p0;
        *(__nv_bfloat162*)&g_wproj[i4 + 2] = p1;
    }
}

// ---------------- kernel 2: QKV GEMM 4096x1152x384, CTA 64x128, 3-stage, 1 sync/iter ----------------
__global__ __launch_bounds__(256) void k_qkv(
        const float* __restrict__ a_qkv_a, const float* __restrict__ a_qkv_w,
        const float* __restrict__ a_q, const float* __restrict__ a_k,
        const float* __restrict__ a_v) {
    __shared__ bf16 sA[3][64][40];
    __shared__ bf16 sB[3][128][40];

    int tid = threadIdx.x, lane = tid & 31, wid = tid >> 5;
    int wm = wid & 3, wn = wid >> 2;
    int gr = lane >> 2, gc = (lane & 3) * 2;
    int lr_a = lane & 15, lc_a = (lane >> 4) << 3;
    int lr_b = ((lane >> 4) << 3) + (lane & 7), lc_b = ((lane >> 3) & 1) << 3;
    int m0 = blockIdx.x * 64, n0 = blockIdx.y * 128;

    int ra = tid >> 2, ca = (tid & 3) * 8;

    float acc[8][4];
    #pragma unroll
    for (int i = 0; i < 8; i++)
        #pragma unroll
        for (int c = 0; c < 4; c++) acc[i][c] = 0.f;

    #pragma unroll
    for (int p = 0; p < 2; p++) {
        int kc0 = p * 32;
        cpa16(sptr(&sA[p][ra][ca]), &g_xq[(size_t)(m0 + ra) * CC + kc0 + ca]);
        cpa16(sptr(&sB[p][ra][ca]), &g_wqkv[(size_t)(n0 + ra) * CC + kc0 + ca]);
        cpa16(sptr(&sB[p][ra + 64][ca]), &g_wqkv[(size_t)(n0 + ra + 64) * CC + kc0 + ca]);
        cpcommit();
    }

    for (int kt = 0; kt < 12; kt++) {
        if (kt <= 9) cpwait<1>(); else cpwait<0>();
        __syncthreads();
        if (kt <= 9) {
            int st = (kt + 2) % 3, kc0 = (kt + 2) * 32;
            cpa16(sptr(&sA[st][ra][ca]), &g_xq[(size_t)(m0 + ra) * CC + kc0 + ca]);
            cpa16(sptr(&sB[st][ra][ca]), &g_wqkv[(size_t)(n0 + ra) * CC + kc0 + ca]);
            cpa16(sptr(&sB[st][ra + 64][ca]), &g_wqkv[(size_t)(n0 + ra + 64) * CC + kc0 + ca]);
            cpcommit();
        }
        int buf = kt % 3;
        #pragma unroll
        for (int kc = 0; kc < 2; kc++) {
            uint32_t af[4];
            ldsm4(af, sptr(&sA[buf][wm * 16 + lr_a][kc * 16 + lc_a]));
            #pragma unroll
            for (int np = 0; np < 4; np++) {
                uint32_t bfr[4];
                ldsm4(bfr, sptr(&sB[buf][wn * 64 + np * 16 + lr_b][kc * 16 + lc_b]));
                mma16816(acc[2 * np], af, bfr[0], bfr[1]);
                mma16816(acc[2 * np + 1], af, bfr[2], bfr[3]);
            }
        }
    }

    int which = (n0 >= 768) ? 2 : (n0 >= 384 ? 1 : 0);
    const float* a3 = (which == 0) ? a_q : (which == 1 ? a_k : a_v);
    float inv3 = 1.f / a3[0];
    float sAB = a_qkv_a[0] * a_qkv_w[0];
    bf16* dst = (which == 0) ? g_q : (which == 1 ? g_k : g_v);
    int ncol0 = n0 - which * CC;
    #pragma unroll
    for (int nc = 0; nc < 8; nc++)
        #pragma unroll
        for (int h2 = 0; h2 < 2; h2++) {
            int row = m0 + wm * 16 + gr + h2 * 8;
            int col = ncol0 + wn * 64 + nc * 8 + gc;
            int b = row >> 11, n = row & 2047;
            int h = col >> 6, d = col & 63;
            __nv_bfloat162 pr;
            pr.x = __float2bfloat16(qlvl(acc[nc][2 * h2] * sAB, inv3));
            pr.y = __float2bfloat16(qlvl(acc[nc][2 * h2 + 1] * sAB, inv3));
            *(__nv_bfloat162*)&dst[(((size_t)(b * HH + h)) * NN + n) * DD + d] = pr;
        }
}

// ---------------- kernel 3a: attention pass 1 — partial row sums over half the KV range ----------------
__global__ __launch_bounds__(128) void k_attn1(
        const float* __restrict__ a_q, const float* __restrict__ a_k,
        const float* __restrict__ a_attn) {
    __shared__ bf16 stg[4][64][72];
    __shared__ float lut[256];

    int tid = threadIdx.x, lane = tid & 31, wid = tid >> 5;
    int gr = lane >> 2;
    int lr_a = lane & 15, lc_a = (lane >> 4) << 3;
    int lr_b = ((lane >> 4) << 3) + (lane & 7), lc_b = ((lane >> 3) & 1) << 3;
    int bh = blockIdx.y;
    int rt0 = blockIdx.x * 64;
    int z = blockIdx.z;
    int wr = wid * 16;

    float aat = a_attn[0];
    float fsc = a_q[0] * a_k[0] * 0.125f / aat;

    #pragma unroll
    for (int i = tid; i < 256; i += 128) lut[i] = expf(-(float)i * aat);

    const bf16* kbase = g_k + (size_t)bh * NN * DD + (size_t)z * 16 * 64 * DD;

    // stage Q into stg[0], build resident A fragments
    const bf16* qptr = g_q + ((size_t)bh * NN + rt0) * DD;
    #pragma unroll
    for (int t = 0; t < 4; t++) {
        int idx = tid + t * 128;
        int r = idx >> 3, c8 = (idx & 7) * 8;
        *(uint4*)&stg[0][r][c8] = *(const uint4*)&qptr[(size_t)r * DD + c8];
    }
    __syncthreads();
    uint32_t qf[4][4];
    #pragma unroll
    for (int kc = 0; kc < 4; kc++)
        ldsm4(qf[kc], sptr(&stg[0][wr + lr_a][kc * 16 + lc_a]));
    __syncthreads();

    float tl[2] = {0.f, 0.f};

    // prologue: prefetch K tiles 0,1,2 into stages 0,1,2
    #pragma unroll
    for (int p = 0; p < 3; p++) {
        const bf16* kp = kbase + (size_t)p * 64 * DD;
        #pragma unroll
        for (int t = 0; t < 4; t++) {
            int idx = tid + t * 128;
            int r = idx >> 3, c8 = (idx & 7) * 8;
            cpa16(sptr(&stg[p][r][c8]), &kp[(size_t)r * DD + c8]);
        }
        cpcommit();
    }

    for (int ct = 0; ct < 16; ct++) {
        if (ct <= 12) cpwait<2>(); else cpwait<0>();
        __syncthreads();
        if (ct <= 12) {
            const bf16* kp = kbase + (size_t)(ct + 3) * 64 * DD;
            int st = (ct + 3) & 3;
            #pragma unroll
            for (int t = 0; t < 4; t++) {
                int idx = tid + t * 128;
                int r = idx >> 3, c8 = (idx & 7) * 8;
                cpa16(sptr(&stg[st][r][c8]), &kp[(size_t)r * DD + c8]);
            }
            cpcommit();
        }
        bf16(*Kb)[72] = stg[ct & 3];

        float sacc[8][4];
        #pragma unroll
        for (int i = 0; i < 8; i++)
            #pragma unroll
            for (int c = 0; c < 4; c++) sacc[i][c] = 0.f;
        #pragma unroll
        for (int ks = 0; ks < 4; ks++)
            #pragma unroll
            for (int np = 0; np < 4; np++) {
                uint32_t bfr[4];
                ldsm4(bfr, sptr(&Kb[np * 16 + lr_b][ks * 16 + lc_b]));
                mma16816(sacc[2 * np], qf[ks], bfr[0], bfr[1]);
                mma16816(sacc[2 * np + 1], qf[ks], bfr[2], bfr[3]);
            }

        #pragma unroll
        for (int nc = 0; nc < 8; nc++)
            #pragma unroll
            for (int h2 = 0; h2 < 2; h2++) {
                int l0 = __float2int_rn(fminf(fmaxf(sacc[nc][2 * h2] * fsc, -128.f), 127.f));
                int l1 = __float2int_rn(fminf(fmaxf(sacc[nc][2 * h2 + 1] * fsc, -128.f), 127.f));
                tl[h2] += lut[127 - l0] + lut[127 - l1];
            }
    }

    // quad sum-reduce; quad leaders publish partial row sums
    #pragma unroll
    for (int h2 = 0; h2 < 2; h2++) {
        tl[h2] += __shfl_xor_sync(0xffffffff, tl[h2], 1);
        tl[h2] += __shfl_xor_sync(0xffffffff, tl[h2], 2);
    }
    if ((lane & 3) == 0) {
        g_lp[z][bh][rt0 + wr + gr] = tl[0];
        g_lp[z][bh][rt0 + wr + gr + 8] = tl[1];
    }
}

// ---------------- kernel 3b: attention pass 2 — recompute S, P in regs, P*V ----------------
__global__ __launch_bounds__(128) void k_attn2(
        const float* __restrict__ a_q, const float* __restrict__ a_k,
        const float* __restrict__ a_attn, const float* __restrict__ a_attn2,
        const float* __restrict__ a_v, const float* __restrict__ a_proj_a) {
    __shared__ bf16 stg[4][64][72];
    __shared__ float lut[256];

    int tid = threadIdx.x, lane = tid & 31, wid = tid >> 5;
    int gr = lane >> 2, gc = (lane & 3) * 2;
    int lr_a = lane & 15, lc_a = (lane >> 4) << 3;
    int lr_b = ((lane >> 4) << 3) + (lane & 7), lc_b = ((lane >> 3) & 1) << 3;
    int bh = blockIdx.y;
    int rt0 = blockIdx.x * 64;
    int wr = wid * 16;

    float aat = a_attn[0];
    float fsc = a_q[0] * a_k[0] * 0.125f / aat;

    #pragma unroll
    for (int i = tid; i < 256; i += 128) lut[i] = expf(-(float)i * aat);

    const bf16* kbase = g_k + (size_t)bh * NN * DD;
    const bf16* vbase = g_v + (size_t)bh * NN * DD;

    // stage Q into stg[0], build resident A fragments
    const bf16* qptr = g_q + ((size_t)bh * NN + rt0) * DD;
    #pragma unroll
    for (int t = 0; t < 4; t++) {
        int idx = tid + t * 128;
        int r = idx >> 3, c8 = (idx & 7) * 8;
        *(uint4*)&stg[0][r][c8] = *(const uint4*)&qptr[(size_t)r * DD + c8];
    }
    __syncthreads();
    uint32_t qf[4][4];
    #pragma unroll
    for (int kc = 0; kc < 4; kc++)
        ldsm4(qf[kc], sptr(&stg[0][wr + lr_a][kc * 16 + lc_a]));
    __syncthreads();

    // prologue: K0 -> stg[0], V0 -> stg[2]
    #pragma unroll
    for (int t = 0; t < 4; t++) {
        int idx = tid + t * 128;
        int r = idx >> 3, c8 = (idx & 7) * 8;
        cpa16(sptr(&stg[0][r][c8]), &kbase[(size_t)r * DD + c8]);
        cpa16(sptr(&stg[2][r][c8]), &vbase[(size_t)r * DD + c8]);
    }
    cpcommit();

    // per-row inverse sums from the two partials (overlaps TMA prologue)
    float inva2 = 1.f / a_attn2[0];
    float liq[2];
    {
        int r0 = rt0 + wr + gr;
        liq[0] = inva2 / (g_lp[0][bh][r0] + g_lp[1][bh][r0]);
        liq[1] = inva2 / (g_lp[0][bh][r0 + 8] + g_lp[1][bh][r0 + 8]);
    }

    float oacc[8][4];
    #pragma unroll
    for (int i = 0; i < 8; i++)
        #pragma unroll
        for (int c = 0; c < 4; c++) oacc[i][c] = 0.f;

    for (int ct = 0; ct < 32; ct++) {
        cpwait<0>();
        __syncthreads();
        if (ct < 31) {
            const bf16* kp = kbase + (size_t)(ct + 1) * 64 * DD;
            const bf16* vp = vbase + (size_t)(ct + 1) * 64 * DD;
            int stk = (ct + 1) & 1, stv = 2 + ((ct + 1) & 1);
            #pragma unroll
            for (int t = 0; t < 4; t++) {
                int idx = tid + t * 128;
                int r = idx >> 3, c8 = (idx & 7) * 8;
                cpa16(sptr(&stg[stk][r][c8]), &kp[(size_t)r * DD + c8]);
                cpa16(sptr(&stg[stv][r][c8]), &vp[(size_t)r * DD + c8]);
            }
            cpcommit();
        }
        bf16(*Kb)[72] = stg[ct & 1];
        bf16(*Vb)[72] = stg[2 + (ct & 1)];

        float sacc[8][4];
        #pragma unroll
        for (int i = 0; i < 8; i++)
            #pragma unroll
            for (int c = 0; c < 4; c++) sacc[i][c] = 0.f;
        #pragma unroll
        for (int ks = 0; ks < 4; ks++)
            #pragma unroll
            for (int np = 0; np < 4; np++) {
                uint32_t bfr[4];
                ldsm4(bfr, sptr(&Kb[np * 16 + lr_b][ks * 16 + lc_b]));
                mma16816(sacc[2 * np], qf[ks], bfr[0], bfr[1]);
                mma16816(sacc[2 * np + 1], qf[ks], bfr[2], bfr[3]);
            }

        // S fragments (f32) -> P level fragments (bf16 A-layout), in registers
        uint32_t pf[4][4];
        #pragma unroll
        for (int kc = 0; kc < 4; kc++) {
            int nc = 2 * kc, ncb = 2 * kc + 1;
            #pragma unroll
            for (int slot = 0; slot < 4; slot++) {
                int src = (slot & 2) ? ncb : nc;
                int h2 = slot & 1;
                float s0 = (h2 ? sacc[src][2] : sacc[src][0]);
                float s1 = (h2 ? sacc[src][3] : sacc[src][1]);
                int l0 = __float2int_rn(fminf(fmaxf(s0 * fsc, -128.f), 127.f));
                int l1 = __float2int_rn(fminf(fmaxf(s1 * fsc, -128.f), 127.f));
                float p0 = rintf(fminf(lut[127 - l0] * liq[h2], 127.f));
                float p1 = rintf(fminf(lut[127 - l1] * liq[h2], 127.f));
                __nv_bfloat162 pr;
                pr.x = __float2bfloat16(p0);
                pr.y = __float2bfloat16(p1);
                pf[kc][slot] = *(uint32_t*)&pr;
            }
        }

        // P (16x64) x V (64x64): B fragments via ldmatrix.trans
        #pragma unroll
        for (int ks = 0; ks < 4; ks++)
            #pragma unroll
            for (int np = 0; np < 4; np++) {
                uint32_t bfr[4];
                ldsm4t(bfr, sptr(&Vb[ks * 16 + lr_a][np * 16 + lc_a]));
                mma16816(oacc[2 * np], pf[ks], bfr[0], bfr[1]);
                mma16816(oacc[2 * np + 1], pf[ks], bfr[2], bfr[3]);
            }
    }

    // epilogue: scale by a_attn2*a_v, quantize with a_proj_a, store [B,N,C] levels
    int b = bh / HH, h = bh % HH;
    float so = a_attn2[0] * a_v[0];
    float invpa = 1.f / a_proj_a[0];
    #pragma unroll
    for (int nc = 0; nc < 8; nc++)
        #pragma unroll
        for (int h2 = 0; h2 < 2; h2++) {
            int n = rt0 + wr + gr + h2 * 8;
            int d = nc * 8 + gc;
            __nv_bfloat162 pr;
            pr.x = __float2bfloat16(qlvl(oacc[nc][2 * h2] * so, invpa));
            pr.y = __float2bfloat16(qlvl(oacc[nc][2 * h2 + 1] * so, invpa));
            *(__nv_bfloat162*)&g_o[((size_t)(b * NN + n)) * CC + h * 64 + d] = pr;
        }
}

// ---------------- kernel 4: projection GEMM 4096x384x384 + bias, CTA 64x64, 3-stage ----------------
__global__ __launch_bounds__(256) void k_proj(
        float* __restrict__ out, const float* __restrict__ bproj,
        const float* __restrict__ a_proj_a, const float* __restrict__ a_proj_w) {
    __shared__ bf16 sA[3][64][40];
    __shared__ bf16 sB[3][64][40];

    int tid = threadIdx.x, lane = tid & 31, wid = tid >> 5;
    int wm = wid & 3, wn = wid >> 2;
    int gr = lane >> 2, gc = (lane & 3) * 2;
    int lr_a = lane & 15, lc_a = (lane >> 4) << 3;
    int lr_b = ((lane >> 4) << 3) + (lane & 7), lc_b = ((lane >> 3) & 1) << 3;
    int m0 = blockIdx.x * 64, n0 = blockIdx.y * 64;

    int ra = tid >> 2, ca = (tid & 3) * 8;

    float acc[4][4];
    #pragma unroll
    for (int i = 0; i < 4; i++)
        #pragma unroll
        for (int c = 0; c < 4; c++) acc[i][c] = 0.f;

    #pragma unroll
    for (int p = 0; p < 2; p++) {
        int kc0 = p * 32;
        cpa16(sptr(&sA[p][ra][ca]), &g_o[(size_t)(m0 + ra) * CC + kc0 + ca]);
        cpa16(sptr(&sB[p][ra][ca]), &g_wproj[(size_t)(n0 + ra) * CC + kc0 + ca]);
        cpcommit();
    }

    for (int kt = 0; kt < 12; kt++) {
        if (kt <= 9) cpwait<1>(); else cpwait<0>();
        __syncthreads();
        if (kt <= 9) {
            int st = (kt + 2) % 3, kc0 = (kt + 2) * 32;
            cpa16(sptr(&sA[st][ra][ca]), &g_o[(size_t)(m0 + ra) * CC + kc0 + ca]);
            cpa16(sptr(&sB[st][ra][ca]), &g_wproj[(size_t)(n0 + ra) * CC + kc0 + ca]);
            cpcommit();
        }
        int buf = kt % 3;
        #pragma unroll
        for (int kc = 0; kc < 2; kc++) {
            uint32_t af[4];
            ldsm4(af, sptr(&sA[buf][wm * 16 + lr_a][kc * 16 + lc_a]));
            #pragma unroll
            for (int np = 0; np < 2; np++) {
                uint32_t bfr[4];
                ldsm4(bfr, sptr(&sB[buf][wn * 32 + np * 16 + lr_b][kc * 16 + lc_b]));
                mma16816(acc[2 * np], af, bfr[0], bfr[1]);
                mma16816(acc[2 * np + 1], af, bfr[2], bfr[3]);
            }
        }
    }

    float sc = a_proj_a[0] * a_proj_w[0];
    #pragma unroll
    for (int jj = 0; jj < 4; jj++)
        #pragma unroll
        for (int h2 = 0; h2 < 2; h2++) {
            int row = m0 + wm * 16 + gr + h2 * 8;
            int col = n0 + wn * 32 + jj * 8 + gc;
            float2 r2;
            r2.x = acc[jj][2 * h2] * sc + bproj[col];
            r2.y = acc[jj][2 * h2 + 1] * sc + bproj[col + 1];
            *(float2*)&out[(size_t)row * CC + col] = r2;
        }
}

// ---------------- launch ----------------
extern "C" void kernel_launch(void* const* d_in, const int* in_sizes, int n_in,
                              void* d_out, int out_size) {
    const float* x        = (const float*)d_in[0];
    const float* wqkv     = (const float*)d_in[1];
    const float* wproj    = (const float*)d_in[2];
    const float* bproj    = (const float*)d_in[3];
    const float* a_qkv_w  = (const float*)d_in[4];
    const float* a_qkv_a  = (const float*)d_in[5];
    const float* a_proj_w = (const float*)d_in[6];
    const float* a_proj_a = (const float*)d_in[7];
    const float* a_q      = (const float*)d_in[8];
    const float* a_k      = (const float*)d_in[9];
    const float* a_v      = (const float*)d_in[10];
    const float* a_attn   = (const float*)d_in[11];
    const float* a_attn2  = (const float*)d_in[12];
    float* out = (float*)d_out;

    k_quant<<<(MM * CC / 4 + 255) / 256, 256>>>(x, wqkv, wproj, a_qkv_w, a_proj_w, a_qkv_a);
    k_qkv<<<dim3(64, 9), 256>>>(a_qkv_a, a_qkv_w, a_q, a_k, a_v);
    k_attn1<<<dim3(32, 12, 2), 128>>>(a_q, a_k, a_attn);
    k_attn2<<<dim3(32, 12), 128>>>(a_q, a_k, a_attn, a_attn2, a_v, a_proj_a);
    k_proj<<<dim3(64, 6), 256>>>(out, bproj, a_proj_a, a_proj_w);
}

// round 15
// speedup vs baseline: 1.6916x; 1.2065x over previous
#include <cuda_runtime.h>
#include <cuda_bf16.h>
#include <cstdint>
#include <math.h>

#define BB 2
#define NN 2048
#define CC 384
#define HH 6
#define DD 64
#define TCC 1152   // 3*C
#define MM 4096    // B*N

typedef __nv_bfloat16 bf16;

// ---------------- device scratch ----------------
__device__ bf16 g_wqkv[TCC * CC];
__device__ bf16 g_wproj[CC * CC];
__device__ bf16 g_xq[(size_t)MM * CC];
__device__ bf16 g_q[BB * HH * NN * DD];
__device__ bf16 g_k[BB * HH * NN * DD];
__device__ bf16 g_v[BB * HH * NN * DD];
__device__ bf16 g_o[(size_t)MM * CC];

// ---------------- helpers ----------------
__device__ __forceinline__ float qlvl(float x, float inv_alpha) {
    float s = x * inv_alpha;
    s = fminf(fmaxf(s, -128.f), 127.f);
    return rintf(s);
}

// round-to-nearest-even + clamp [0,255] in one CVT
__device__ __forceinline__ uint32_t cvt_u8_sat(float x) {
    uint32_t r;
    asm("cvt.rni.sat.u8.f32 %0, %1;" : "=r"(r) : "f"(x));
    return r;
}
// round-to-nearest-even + clamp [-128,127] in one CVT
__device__ __forceinline__ int cvt_s8_sat(float x) {
    int r;
    asm("cvt.rni.sat.s8.f32 %0, %1;" : "=r"(r) : "f"(x));
    return r;
}
// pack two f32 into bf16x2 {hi=b, lo=a}
__device__ __forceinline__ uint32_t pack_bf16x2(float a, float b) {
    uint32_t r;
    asm("cvt.rn.bf16x2.f32 %0, %1, %2;" : "=r"(r) : "f"(b), "f"(a));
    return r;
}

__device__ __forceinline__ void mma16816(float* c, const uint32_t* a,
                                         uint32_t b0, uint32_t b1) {
    asm volatile(
        "mma.sync.aligned.m16n8k16.row.col.f32.bf16.bf16.f32 "
        "{%0,%1,%2,%3}, {%4,%5,%6,%7}, {%8,%9}, {%0,%1,%2,%3};\n"
        : "+f"(c[0]), "+f"(c[1]), "+f"(c[2]), "+f"(c[3])
        : "r"(a[0]), "r"(a[1]), "r"(a[2]), "r"(a[3]), "r"(b0), "r"(b1));
}

__device__ __forceinline__ uint32_t sptr(const void* p) {
    return (uint32_t)__cvta_generic_to_shared(p);
}
__device__ __forceinline__ void ldsm4(uint32_t* r, uint32_t addr) {
    asm volatile("ldmatrix.sync.aligned.m8n8.x4.shared.b16 {%0,%1,%2,%3},[%4];\n"
                 : "=r"(r[0]), "=r"(r[1]), "=r"(r[2]), "=r"(r[3]) : "r"(addr));
}
__device__ __forceinline__ void ldsm4t(uint32_t* r, uint32_t addr) {
    asm volatile("ldmatrix.sync.aligned.m8n8.x4.trans.shared.b16 {%0,%1,%2,%3},[%4];\n"
                 : "=r"(r[0]), "=r"(r[1]), "=r"(r[2]), "=r"(r[3]) : "r"(addr));
}
__device__ __forceinline__ void cpa16(uint32_t d, const void* s) {
    asm volatile("cp.async.cg.shared.global [%0], [%1], 16;\n" :: "r"(d), "l"(s));
}
__device__ __forceinline__ void cpcommit() {
    asm volatile("cp.async.commit_group;\n");
}
template <int N>
__device__ __forceinline__ void cpwait() {
    asm volatile("cp.async.wait_group %0;\n" :: "n"(N));
}

// ---------------- kernel 1: quantize weights + x to bf16 levels ----------------
__global__ __launch_bounds__(256) void k_quant(
        const float* __restrict__ x,
        const float* __restrict__ wqkv, const float* __restrict__ wproj,
        const float* __restrict__ a_qkv_w, const float* __restrict__ a_proj_w,
        const float* __restrict__ a_qkv_a) {
    float i1 = 1.f / a_qkv_w[0];
    float i2 = 1.f / a_proj_w[0];
    float i3 = 1.f / a_qkv_a[0];
    int i4 = (blockIdx.x * 256 + threadIdx.x) * 4;

    if (i4 < MM * CC) {
        float4 v = *(const float4*)&x[i4];
        __nv_bfloat162 p0, p1;
        p0.x = __float2bfloat16(qlvl(v.x, i3));
        p0.y = __float2bfloat16(qlvl(v.y, i3));
        p1.x = __float2bfloat16(qlvl(v.z, i3));
        p1.y = __float2bfloat16(qlvl(v.w, i3));
        *(__nv_bfloat162*)&g_xq[i4] = p0;
        *(__nv_bfloat162*)&g_xq[i4 + 2] = p1;
    }
    if (i4 < TCC * CC) {
        float4 v = *(const float4*)&wqkv[i4];
        __nv_bfloat162 p0, p1;
        p0.x = __float2bfloat16(qlvl(v.x, i1));
        p0.y = __float2bfloat16(qlvl(v.y, i1));
        p1.x = __float2bfloat16(qlvl(v.z, i1));
        p1.y = __float2bfloat16(qlvl(v.w, i1));
        *(__nv_bfloat162*)&g_wqkv[i4] = p0;
        *(__nv_bfloat162*)&g_wqkv[i4 + 2] = p1;
    }
    if (i4 < CC * CC) {
        float4 v = *(const float4*)&wproj[i4];
        __nv_bfloat162 p0, p1;
        p0.x = __float2bfloat16(qlvl(v.x, i2));
        p0.y = __float2bfloat16(qlvl(v.y, i2));
        p1.x = __float2bfloat16(qlvl(v.z, i2));
        p1.y = __float2bfloat16(qlvl(v.w, i2));
        *(__nv_bfloat162*)&g_wproj[i4] = p0;
        *(__nv_bfloat162*)&g_wproj[i4 + 2] = p1;
    }
}

// ---------------- kernel 2: QKV GEMM 4096x1152x384, CTA 64x128, 3-stage, 1 sync/iter ----------------
__global__ __launch_bounds__(256) void k_qkv(
        const float* __restrict__ a_qkv_a, const float* __restrict__ a_qkv_w,
        const float* __restrict__ a_q, const float* __restrict__ a_k,
        const float* __restrict__ a_v) {
    __shared__ bf16 sA[3][64][40];
    __shared__ bf16 sB[3][128][40];

    int tid = threadIdx.x, lane = tid & 31, wid = tid >> 5;
    int wm = wid & 3, wn = wid >> 2;
    int gr = lane >> 2, gc = (lane & 3) * 2;
    int lr_a = lane & 15, lc_a = (lane >> 4) << 3;
    int lr_b = ((lane >> 4) << 3) + (lane & 7), lc_b = ((lane >> 3) & 1) << 3;
    int m0 = blockIdx.x * 64, n0 = blockIdx.y * 128;

    int ra = tid >> 2, ca = (tid & 3) * 8;

    float acc[8][4];
    #pragma unroll
    for (int i = 0; i < 8; i++)
        #pragma unroll
        for (int c = 0; c < 4; c++) acc[i][c] = 0.f;

    #pragma unroll
    for (int p = 0; p < 2; p++) {
        int kc0 = p * 32;
        cpa16(sptr(&sA[p][ra][ca]), &g_xq[(size_t)(m0 + ra) * CC + kc0 + ca]);
        cpa16(sptr(&sB[p][ra][ca]), &g_wqkv[(size_t)(n0 + ra) * CC + kc0 + ca]);
        cpa16(sptr(&sB[p][ra + 64][ca]), &g_wqkv[(size_t)(n0 + ra + 64) * CC + kc0 + ca]);
        cpcommit();
    }

    for (int kt = 0; kt < 12; kt++) {
        if (kt <= 9) cpwait<1>(); else cpwait<0>();
        __syncthreads();
        if (kt <= 9) {
            int st = (kt + 2) % 3, kc0 = (kt + 2) * 32;
            cpa16(sptr(&sA[st][ra][ca]), &g_xq[(size_t)(m0 + ra) * CC + kc0 + ca]);
            cpa16(sptr(&sB[st][ra][ca]), &g_wqkv[(size_t)(n0 + ra) * CC + kc0 + ca]);
            cpa16(sptr(&sB[st][ra + 64][ca]), &g_wqkv[(size_t)(n0 + ra + 64) * CC + kc0 + ca]);
            cpcommit();
        }
        int buf = kt % 3;
        #pragma unroll
        for (int kc = 0; kc < 2; kc++) {
            uint32_t af[4];
            ldsm4(af, sptr(&sA[buf][wm * 16 + lr_a][kc * 16 + lc_a]));
            #pragma unroll
            for (int np = 0; np < 4; np++) {
                uint32_t bfr[4];
                ldsm4(bfr, sptr(&sB[buf][wn * 64 + np * 16 + lr_b][kc * 16 + lc_b]));
                mma16816(acc[2 * np], af, bfr[0], bfr[1]);
                mma16816(acc[2 * np + 1], af, bfr[2], bfr[3]);
            }
        }
    }

    int which = (n0 >= 768) ? 2 : (n0 >= 384 ? 1 : 0);
    const float* a3 = (which == 0) ? a_q : (which == 1 ? a_k : a_v);
    float inv3 = 1.f / a3[0];
    float sAB = a_qkv_a[0] * a_qkv_w[0];
    bf16* dst = (which == 0) ? g_q : (which == 1 ? g_k : g_v);
    int ncol0 = n0 - which * CC;
    #pragma unroll
    for (int nc = 0; nc < 8; nc++)
        #pragma unroll
        for (int h2 = 0; h2 < 2; h2++) {
            int row = m0 + wm * 16 + gr + h2 * 8;
            int col = ncol0 + wn * 64 + nc * 8 + gc;
            int b = row >> 11, n = row & 2047;
            int h = col >> 6, d = col & 63;
            __nv_bfloat162 pr;
            pr.x = __float2bfloat16(qlvl(acc[nc][2 * h2] * sAB, inv3));
            pr.y = __float2bfloat16(qlvl(acc[nc][2 * h2 + 1] * sAB, inv3));
            *(__nv_bfloat162*)&dst[(((size_t)(b * HH + h)) * NN + n) * DD + d] = pr;
        }
}

// ---------------- kernel 3: fused attention, 64 Q rows/CTA, 4 warps, fixed m ----------------
// pass 1: 4-stage K ring; pass 2: 2-stage K+V; 1 sync/iter; sat-CVT softmax chain.
__global__ __launch_bounds__(128) void k_attn(
        const float* __restrict__ a_q, const float* __restrict__ a_k,
        const float* __restrict__ a_attn, const float* __restrict__ a_attn2,
        const float* __restrict__ a_v, const float* __restrict__ a_proj_a) {
    __shared__ bf16 stg[4][64][72];
    __shared__ float lutS[256];   // lutS[i] = exp((i-255)*a), index i = level+128

    int tid = threadIdx.x, lane = tid & 31, wid = tid >> 5;
    int gr = lane >> 2, gc = (lane & 3) * 2;
    int lr_a = lane & 15, lc_a = (lane >> 4) << 3;
    int lr_b = ((lane >> 4) << 3) + (lane & 7), lc_b = ((lane >> 3) & 1) << 3;
    int bh = blockIdx.y;
    int rt0 = blockIdx.x * 64;
    int wr = wid * 16;

    float aat = a_attn[0];
    float fsc = a_q[0] * a_k[0] * 0.125f / aat;   // scale = D^-0.5 = 1/8

    #pragma unroll
    for (int i = tid; i < 256; i += 128) lutS[i] = expf((float)(i - 255) * aat);

    const bf16* kbase = g_k + (size_t)bh * NN * DD;
    const bf16* vbase = g_v + (size_t)bh * NN * DD;

    // stage Q into stg[0], build resident A fragments
    const bf16* qptr = g_q + ((size_t)bh * NN + rt0) * DD;
    #pragma unroll
    for (int t = 0; t < 4; t++) {
        int idx = tid + t * 128;
        int r = idx >> 3, c8 = (idx & 7) * 8;
        *(uint4*)&stg[0][r][c8] = *(const uint4*)&qptr[(size_t)r * DD + c8];
    }
    __syncthreads();
    uint32_t qf[4][4];
    #pragma unroll
    for (int kc = 0; kc < 4; kc++)
        ldsm4(qf[kc], sptr(&stg[0][wr + lr_a][kc * 16 + lc_a]));
    __syncthreads();

    float tl[2] = {0.f, 0.f};

    // pass-1 prologue: prefetch K tiles 0,1,2
    #pragma unroll
    for (int p = 0; p < 3; p++) {
        const bf16* kp = kbase + (size_t)p * 64 * DD;
        #pragma unroll
        for (int t = 0; t < 4; t++) {
            int idx = tid + t * 128;
            int r = idx >> 3, c8 = (idx & 7) * 8;
            cpa16(sptr(&stg[p][r][c8]), &kp[(size_t)r * DD + c8]);
        }
        cpcommit();
    }

    // ---------- pass 1: row sums of exp((l-127)*a) ----------
    for (int ct = 0; ct < 32; ct++) {
        if (ct <= 28) cpwait<2>(); else cpwait<0>();
        __syncthreads();
        if (ct <= 28) {
            const bf16* kp = kbase + (size_t)(ct + 3) * 64 * DD;
            int st = (ct + 3) & 3;
            #pragma unroll
            for (int t = 0; t < 4; t++) {
                int idx = tid + t * 128;
                int r = idx >> 3, c8 = (idx & 7) * 8;
                cpa16(sptr(&stg[st][r][c8]), &kp[(size_t)r * DD + c8]);
            }
            cpcommit();
        }
        bf16(*Kb)[72] = stg[ct & 3];

        float sacc[8][4];
        #pragma unroll
        for (int i = 0; i < 8; i++)
            #pragma unroll
            for (int c = 0; c < 4; c++) sacc[i][c] = 0.f;
        #pragma unroll
        for (int ks = 0; ks < 4; ks++)
            #pragma unroll
            for (int np = 0; np < 4; np++) {
                uint32_t bfr[4];
                ldsm4(bfr, sptr(&Kb[np * 16 + lr_b][ks * 16 + lc_b]));
                mma16816(sacc[2 * np], qf[ks], bfr[0], bfr[1]);
                mma16816(sacc[2 * np + 1], qf[ks], bfr[2], bfr[3]);
            }

        #pragma unroll
        for (int nc = 0; nc < 8; nc++)
            #pragma unroll
            for (int h2 = 0; h2 < 2; h2++) {
                uint32_t i0 = cvt_u8_sat(fmaf(sacc[nc][2 * h2], fsc, 128.f));
                uint32_t i1 = cvt_u8_sat(fmaf(sacc[nc][2 * h2 + 1], fsc, 128.f));
                tl[h2] += lutS[i0] + lutS[i1];
            }
    }

    // quad sum-reduce -> lane-local inverse sums
    float inva2 = 1.f / a_attn2[0];
    float liq[2];
    #pragma unroll
    for (int h2 = 0; h2 < 2; h2++) {
        tl[h2] += __shfl_xor_sync(0xffffffff, tl[h2], 1);
        tl[h2] += __shfl_xor_sync(0xffffffff, tl[h2], 2);
        liq[h2] = inva2 / tl[h2];
    }

    // pass-2 prologue: K0 -> stg[0], V0 -> stg[2]
    #pragma unroll
    for (int t = 0; t < 4; t++) {
        int idx = tid + t * 128;
        int r = idx >> 3, c8 = (idx & 7) * 8;
        cpa16(sptr(&stg[0][r][c8]), &kbase[(size_t)r * DD + c8]);
        cpa16(sptr(&stg[2][r][c8]), &vbase[(size_t)r * DD + c8]);
    }
    cpcommit();

    // ---------- pass 2: recompute S, P in registers, P*V ----------
    float oacc[8][4];
    #pragma unroll
    for (int i = 0; i < 8; i++)
        #pragma unroll
        for (int c = 0; c < 4; c++) oacc[i][c] = 0.f;

    for (int ct = 0; ct < 32; ct++) {
        cpwait<0>();
        __syncthreads();
        if (ct < 31) {
            const bf16* kp = kbase + (size_t)(ct + 1) * 64 * DD;
            const bf16* vp = vbase + (size_t)(ct + 1) * 64 * DD;
            int stk = (ct + 1) & 1, stv = 2 + ((ct + 1) & 1);
            #pragma unroll
            for (int t = 0; t < 4; t++) {
                int idx = tid + t * 128;
                int r = idx >> 3, c8 = (idx & 7) * 8;
                cpa16(sptr(&stg[stk][r][c8]), &kp[(size_t)r * DD + c8]);
                cpa16(sptr(&stg[stv][r][c8]), &vp[(size_t)r * DD + c8]);
            }
            cpcommit();
        }
        bf16(*Kb)[72] = stg[ct & 1];
        bf16(*Vb)[72] = stg[2 + (ct & 1)];

        float sacc[8][4];
        #pragma unroll
        for (int i = 0; i < 8; i++)
            #pragma unroll
            for (int c = 0; c < 4; c++) sacc[i][c] = 0.f;
        #pragma unroll
        for (int ks = 0; ks < 4; ks++)
            #pragma unroll
            for (int np = 0; np < 4; np++) {
                uint32_t bfr[4];
                ldsm4(bfr, sptr(&Kb[np * 16 + lr_b][ks * 16 + lc_b]));
                mma16816(sacc[2 * np], qf[ks], bfr[0], bfr[1]);
                mma16816(sacc[2 * np + 1], qf[ks], bfr[2], bfr[3]);
            }

        // S fragments (f32) -> P level fragments (bf16 A-layout), in registers
        uint32_t pf[4][4];
        #pragma unroll
        for (int kc = 0; kc < 4; kc++) {
            int nc = 2 * kc, ncb = 2 * kc + 1;
            #pragma unroll
            for (int slot = 0; slot < 4; slot++) {
                int src = (slot & 2) ? ncb : nc;
                int h2 = slot & 1;
                float s0 = (h2 ? sacc[src][2] : sacc[src][0]);
                float s1 = (h2 ? sacc[src][3] : sacc[src][1]);
                uint32_t i0 = cvt_u8_sat(fmaf(s0, fsc, 128.f));
                uint32_t i1 = cvt_u8_sat(fmaf(s1, fsc, 128.f));
                // P >= 0, s8-sat clamps at 127 and rounds rni in one op
                int p0 = cvt_s8_sat(lutS[i0] * liq[h2]);
                int p1 = cvt_s8_sat(lutS[i1] * liq[h2]);
                pf[kc][slot] = pack_bf16x2((float)p0, (float)p1);
            }
        }

        // P (16x64) x V (64x64): B fragments via ldmatrix.trans
        #pragma unroll
        for (int ks = 0; ks < 4; ks++)
            #pragma unroll
            for (int np = 0; np < 4; np++) {
                uint32_t bfr[4];
                ldsm4t(bfr, sptr(&Vb[ks * 16 + lr_a][np * 16 + lc_a]));
                mma16816(oacc[2 * np], pf[ks], bfr[0], bfr[1]);
                mma16816(oacc[2 * np + 1], pf[ks], bfr[2], bfr[3]);
            }
    }

    // epilogue: scale by a_attn2*a_v, quantize with a_proj_a, store [B,N,C] levels
    int b = bh / HH, h = bh % HH;
    float so = a_attn2[0] * a_v[0];
    float invpa = 1.f / a_proj_a[0];
    #pragma unroll
    for (int nc = 0; nc < 8; nc++)
        #pragma unroll
        for (int h2 = 0; h2 < 2; h2++) {
            int n = rt0 + wr + gr + h2 * 8;
            int d = nc * 8 + gc;
            __nv_bfloat162 pr;
            pr.x = __float2bfloat16(qlvl(oacc[nc][2 * h2] * so, invpa));
            pr.y = __float2bfloat16(qlvl(oacc[nc][2 * h2 + 1] * so, invpa));
            *(__nv_bfloat162*)&g_o[((size_t)(b * NN + n)) * CC + h * 64 + d] = pr;
        }
}

// ---------------- kernel 4: projection GEMM 4096x384x384 + bias, CTA 64x64, 3-stage ----------------
__global__ __launch_bounds__(256) void k_proj(
        float* __restrict__ out, const float* __restrict__ bproj,
        const float* __restrict__ a_proj_a, const float* __restrict__ a_proj_w) {
    __shared__ bf16 sA[3][64][40];
    __shared__ bf16 sB[3][64][40];

    int tid = threadIdx.x, lane = tid & 31, wid = tid >> 5;
    int wm = wid & 3, wn = wid >> 2;
    int gr = lane >> 2, gc = (lane & 3) * 2;
    int lr_a = lane & 15, lc_a = (lane >> 4) << 3;
    int lr_b = ((lane >> 4) << 3) + (lane & 7), lc_b = ((lane >> 3) & 1) << 3;
    int m0 = blockIdx.x * 64, n0 = blockIdx.y * 64;

    int ra = tid >> 2, ca = (tid & 3) * 8;

    float acc[4][4];
    #pragma unroll
    for (int i = 0; i < 4; i++)
        #pragma unroll
        for (int c = 0; c < 4; c++) acc[i][c] = 0.f;

    #pragma unroll
    for (int p = 0; p < 2; p++) {
        int kc0 = p * 32;
        cpa16(sptr(&sA[p][ra][ca]), &g_o[(size_t)(m0 + ra) * CC + kc0 + ca]);
        cpa16(sptr(&sB[p][ra][ca]), &g_wproj[(size_t)(n0 + ra) * CC + kc0 + ca]);
        cpcommit();
    }

    for (int kt = 0; kt < 12; kt++) {
        if (kt <= 9) cpwait<1>(); else cpwait<0>();
        __syncthreads();
        if (kt <= 9) {
            int st = (kt + 2) % 3, kc0 = (kt + 2) * 32;
            cpa16(sptr(&sA[st][ra][ca]), &g_o[(size_t)(m0 + ra) * CC + kc0 + ca]);
            cpa16(sptr(&sB[st][ra][ca]), &g_wproj[(size_t)(n0 + ra) * CC + kc0 + ca]);
            cpcommit();
        }
        int buf = kt % 3;
        #pragma unroll
        for (int kc = 0; kc < 2; kc++) {
            uint32_t af[4];
            ldsm4(af, sptr(&sA[buf][wm * 16 + lr_a][kc * 16 + lc_a]));
            #pragma unroll
            for (int np = 0; np < 2; np++) {
                uint32_t bfr[4];
                ldsm4(bfr, sptr(&sB[buf][wn * 32 + np * 16 + lr_b][kc * 16 + lc_b]));
                mma16816(acc[2 * np], af, bfr[0], bfr[1]);
                mma16816(acc[2 * np + 1], af, bfr[2], bfr[3]);
            }
        }
    }

    float sc = a_proj_a[0] * a_proj_w[0];
    #pragma unroll
    for (int jj = 0; jj < 4; jj++)
        #pragma unroll
        for (int h2 = 0; h2 < 2; h2++) {
            int row = m0 + wm * 16 + gr + h2 * 8;
            int col = n0 + wn * 32 + jj * 8 + gc;
            float2 r2;
            r2.x = acc[jj][2 * h2] * sc + bproj[col];
            r2.y = acc[jj][2 * h2 + 1] * sc + bproj[col + 1];
            *(float2*)&out[(size_t)row * CC + col] = r2;
        }
}

// ---------------- launch ----------------
extern "C" void kernel_launch(void* const* d_in, const int* in_sizes, int n_in,
                              void* d_out, int out_size) {
    const float* x        = (const float*)d_in[0];
    const float* wqkv     = (const float*)d_in[1];
    const float* wproj    = (const float*)d_in[2];
    const float* bproj    = (const float*)d_in[3];
    const float* a_qkv_w  = (const float*)d_in[4];
    const float* a_qkv_a  = (const float*)d_in[5];
    const float* a_proj_w = (const float*)d_in[6];
    const float* a_proj_a = (const float*)d_in[7];
    const float* a_q      = (const float*)d_in[8];
    const float* a_k      = (const float*)d_in[9];
    const float* a_v      = (const float*)d_in[10];
    const float* a_attn   = (const float*)d_in[11];
    const float* a_attn2  = (const float*)d_in[12];
    float* out = (float*)d_out;

    k_quant<<<(MM * CC / 4 + 255) / 256, 256>>>(x, wqkv, wproj, a_qkv_w, a_proj_w, a_qkv_a);
    k_qkv<<<dim3(64, 9), 256>>>(a_qkv_a, a_qkv_w, a_q, a_k, a_v);
    k_attn<<<dim3(32, 12), 128>>>(a_q, a_k, a_attn, a_attn2, a_v, a_proj_a);
    k_proj<<<dim3(64, 6), 256>>>(out, bproj, a_proj_a, a_proj_w);
}